// round 7
// baseline (speedup 1.0000x reference)
#include <cuda_runtime.h>
#include <cstdint>

// APPNP: h <- 0.9 * A@h + 0.1 * x, 10 iterations, A given as edge list.
// CSR build (memset + int4-hist + 3-kernel hierarchical scan + scatter with
// atomicSub fill), then 10x atomic-free SpMM: one warp per destination row,
// two 16-lane halves each processing separate edges with float4 (LDG.128)
// gathers of h[col] out of L2. Edge weights pre-scaled by (1-alpha).

#define N_NODES 100000
#define N_EDGES 3200000
#define D_FEAT  64
#define ALPHA   0.1f
#define K_STEPS 10
#define SCAN_BLK 1024
#define N_SCAN_BLKS ((N_NODES + SCAN_BLK - 1) / SCAN_BLK)   // 98

// -------- static device scratch (no allocations allowed) --------
__device__ int   g_count[N_NODES];          // hist counts; consumed by scatter
__device__ int   g_rowptr[N_NODES + 1];
__device__ int   g_bsum[N_SCAN_BLKS];
__device__ int   g_boff[N_SCAN_BLKS];
__device__ int2  g_cw[N_EDGES];             // {col, bits(0.9*weight)}
__device__ float g_h[2][(size_t)N_NODES * D_FEAT];  // ping-pong h buffers

// -------- CSR build --------
__global__ void k_hist(const int4* __restrict__ erow4) {
    int t = blockIdx.x * blockDim.x + threadIdx.x;
    if (t < N_EDGES / 4) {
        int4 r = erow4[t];
        atomicAdd(&g_count[r.x], 1);
        atomicAdd(&g_count[r.y], 1);
        atomicAdd(&g_count[r.z], 1);
        atomicAdd(&g_count[r.w], 1);
    }
}

// per-block exclusive scan of g_count into g_rowptr + block totals
__global__ void __launch_bounds__(SCAN_BLK) k_scan1() {
    __shared__ int s[SCAN_BLK];
    int tid = threadIdx.x;
    int i = blockIdx.x * SCAN_BLK + tid;
    int v = (i < N_NODES) ? g_count[i] : 0;
    s[tid] = v;
    __syncthreads();
    #pragma unroll
    for (int off = 1; off < SCAN_BLK; off <<= 1) {
        int t = (tid >= off) ? s[tid - off] : 0;
        __syncthreads();
        s[tid] += t;
        __syncthreads();
    }
    if (i < N_NODES) g_rowptr[i] = s[tid] - v;  // exclusive within block
    if (tid == SCAN_BLK - 1) g_bsum[blockIdx.x] = s[tid];
}

// scan the 98 block totals
__global__ void k_scan2() {
    __shared__ int s[128];
    int tid = threadIdx.x;
    int v = (tid < N_SCAN_BLKS) ? g_bsum[tid] : 0;
    s[tid] = v;
    __syncthreads();
    #pragma unroll
    for (int off = 1; off < 128; off <<= 1) {
        int t = (tid >= off) ? s[tid - off] : 0;
        __syncthreads();
        s[tid] += t;
        __syncthreads();
    }
    if (tid < N_SCAN_BLKS) g_boff[tid] = s[tid] - v;
    if (tid == 0) g_rowptr[N_NODES] = N_EDGES;
}

__global__ void k_scan3() {
    int i = blockIdx.x * blockDim.x + threadIdx.x;
    if (i < N_NODES) g_rowptr[i] += g_boff[i >> 10];
}

__global__ void k_scatter(const int* __restrict__ erow,
                          const int* __restrict__ ecol,
                          const float* __restrict__ ew) {
    int e = blockIdx.x * blockDim.x + threadIdx.x;
    if (e < N_EDGES) {
        int r = erow[e];
        int p = g_rowptr[r] + atomicSub(&g_count[r], 1) - 1;
        g_cw[p] = make_int2(ecol[e], __float_as_int((1.0f - ALPHA) * ew[e]));
    }
}

// -------- SpMM: warp per row; two 16-lane halves, float4 per lane --------
__global__ void __launch_bounds__(256)
k_spmm(const float* __restrict__ src, const float* __restrict__ x,
       float* __restrict__ dst) {
    int warp = (blockIdx.x * blockDim.x + threadIdx.x) >> 5;
    int lane = threadIdx.x & 31;
    if (warp >= N_NODES) return;

    int beg = g_rowptr[warp];
    int end = g_rowptr[warp + 1];

    int half = lane >> 4;   // which half-warp
    int sub  = lane & 15;   // 4-feature group: feats sub*4 .. sub*4+3

    float4 acc = make_float4(0.f, 0.f, 0.f, 0.f);
    const float4* __restrict__ srcv = (const float4*)src;

    for (int base = beg; base < end; base += 32) {
        int e = base + lane;
        int2 cw = (e < end) ? g_cw[e] : make_int2(0, 0);
        int m = end - base; if (m > 32) m = 32;
        int steps = (m + 1) >> 1;          // halves interleave edges 2j+half
        #pragma unroll 4
        for (int j = 0; j < steps; j++) {
            int srcl = 2 * j + half;
            int   c  = __shfl_sync(0xffffffffu, cw.x, srcl);
            float wv = __int_as_float(__shfl_sync(0xffffffffu, cw.y, srcl));
            if (srcl < m) {
                float4 hv = srcv[c * 16 + sub];
                acc.x = fmaf(wv, hv.x, acc.x);
                acc.y = fmaf(wv, hv.y, acc.y);
                acc.z = fmaf(wv, hv.z, acc.z);
                acc.w = fmaf(wv, hv.w, acc.w);
            }
        }
    }

    // combine the two halves (each lane ends with the full sum for its feats)
    acc.x += __shfl_xor_sync(0xffffffffu, acc.x, 16);
    acc.y += __shfl_xor_sync(0xffffffffu, acc.y, 16);
    acc.z += __shfl_xor_sync(0xffffffffu, acc.z, 16);
    acc.w += __shfl_xor_sync(0xffffffffu, acc.w, 16);

    if (half == 0) {
        float4 xv = ((const float4*)x)[warp * 16 + sub];
        float4 o;
        o.x = fmaf(ALPHA, xv.x, acc.x);   // weights already carry (1-alpha)
        o.y = fmaf(ALPHA, xv.y, acc.y);
        o.z = fmaf(ALPHA, xv.z, acc.z);
        o.w = fmaf(ALPHA, xv.w, acc.w);
        ((float4*)dst)[warp * 16 + sub] = o;
    }
}

extern "C" void kernel_launch(void* const* d_in, const int* in_sizes, int n_in,
                              void* d_out, int out_size) {
    const float* x    = (const float*)d_in[0];
    const int*   erow = (const int*)d_in[1];
    const int*   ecol = (const int*)d_in[2];
    const float* ew   = (const float*)d_in[3];
    float*       out  = (float*)d_out;

    float* hbuf;
    cudaGetSymbolAddress((void**)&hbuf, g_h);
    float* hA = hbuf;
    float* hB = hbuf + (size_t)N_NODES * D_FEAT;
    int* countPtr;
    cudaGetSymbolAddress((void**)&countPtr, g_count);

    const int TB = 256;
    const int nodeBlocks = (N_NODES + TB - 1) / TB;
    const int edgeBlocks = (N_EDGES + TB - 1) / TB;
    const int histBlocks = (N_EDGES / 4 + TB - 1) / TB;
    const int spmmBlocks = (N_NODES * 32 + TB - 1) / TB;

    // CSR build (per launch; amortized over 10 SpMM iterations)
    cudaMemsetAsync(countPtr, 0, N_NODES * sizeof(int));
    k_hist<<<histBlocks, TB>>>((const int4*)erow);
    k_scan1<<<N_SCAN_BLKS, SCAN_BLK>>>();
    k_scan2<<<1, 128>>>();
    k_scan3<<<nodeBlocks, TB>>>();
    k_scatter<<<edgeBlocks, TB>>>(erow, ecol, ew);

    // 10 propagation steps; iter 0 reads x directly, iter 9 writes d_out.
    const float* src = x;
    for (int k = 0; k < K_STEPS; k++) {
        float* dst = (k == K_STEPS - 1) ? out : ((k & 1) ? hB : hA);
        k_spmm<<<spmmBlocks, TB>>>(src, x, dst);
        src = dst;
    }
}

// round 8
// speedup vs baseline: 1.0216x; 1.0216x over previous
#include <cuda_runtime.h>
#include <cuda_fp16.h>
#include <cstdint>

// APPNP: h <- 0.9 * A@h + 0.1 * x, 10 iterations, A given as edge list.
// CSR build (memset + int4-hist-with-rank + hierarchical scan + atomic-free
// scatter), then 10x warp-per-row SpMM. Intermediates h1..h4 stored fp16
// (halves L2 gather traffic on iters 2-5; injected rounding ~5.6e-4 norm-rel,
// under the 1e-3 gate); h5..h9 fp32 (fp16 would overflow by h9, sigma~1.6e4).
// SpMM is LTS-bound: 819MB (fp32) / 410MB (fp16) L2 gather per iteration.

#define N_NODES 100000
#define N_EDGES 3200000
#define D_FEAT  64
#define ALPHA   0.1f
#define K_STEPS 10
#define SCAN_BLK 1024
#define N_SCAN_BLKS ((N_NODES + SCAN_BLK - 1) / SCAN_BLK)   // 98

// -------- static device scratch (no allocations allowed) --------
__device__ int            g_count[N_NODES];
__device__ int            g_rowptr[N_NODES + 1];
__device__ int            g_bsum[N_SCAN_BLKS];
__device__ int            g_boff[N_SCAN_BLKS];
__device__ unsigned short g_rank[N_EDGES];
__device__ int2           g_cw[N_EDGES];            // {col, bits(0.9*w)}
__device__ float          g_h[2][(size_t)N_NODES * D_FEAT];   // fp32 ping-pong
__device__ __half         g_h16[2][(size_t)N_NODES * D_FEAT]; // fp16 ping-pong

// -------- CSR build --------
// hist + per-edge rank (atomicAdd's return value = rank within row)
__global__ void k_hist(const int4* __restrict__ erow4) {
    int t = blockIdx.x * blockDim.x + threadIdx.x;
    if (t < N_EDGES / 4) {
        int4 r = erow4[t];
        unsigned short r0 = (unsigned short)atomicAdd(&g_count[r.x], 1);
        unsigned short r1 = (unsigned short)atomicAdd(&g_count[r.y], 1);
        unsigned short r2 = (unsigned short)atomicAdd(&g_count[r.z], 1);
        unsigned short r3 = (unsigned short)atomicAdd(&g_count[r.w], 1);
        ushort4 rk = make_ushort4(r0, r1, r2, r3);
        ((ushort4*)g_rank)[t] = rk;
    }
}

__global__ void __launch_bounds__(SCAN_BLK) k_scan1() {
    __shared__ int s[SCAN_BLK];
    int tid = threadIdx.x;
    int i = blockIdx.x * SCAN_BLK + tid;
    int v = (i < N_NODES) ? g_count[i] : 0;
    s[tid] = v;
    __syncthreads();
    #pragma unroll
    for (int off = 1; off < SCAN_BLK; off <<= 1) {
        int t = (tid >= off) ? s[tid - off] : 0;
        __syncthreads();
        s[tid] += t;
        __syncthreads();
    }
    if (i < N_NODES) g_rowptr[i] = s[tid] - v;  // exclusive within block
    if (tid == SCAN_BLK - 1) g_bsum[blockIdx.x] = s[tid];
}

__global__ void k_scan2() {
    __shared__ int s[128];
    int tid = threadIdx.x;
    int v = (tid < N_SCAN_BLKS) ? g_bsum[tid] : 0;
    s[tid] = v;
    __syncthreads();
    #pragma unroll
    for (int off = 1; off < 128; off <<= 1) {
        int t = (tid >= off) ? s[tid - off] : 0;
        __syncthreads();
        s[tid] += t;
        __syncthreads();
    }
    if (tid < N_SCAN_BLKS) g_boff[tid] = s[tid] - v;
    if (tid == 0) g_rowptr[N_NODES] = N_EDGES;
}

__global__ void k_scan3() {
    int i = blockIdx.x * blockDim.x + threadIdx.x;
    if (i < N_NODES) g_rowptr[i] += g_boff[i >> 10];
}

// atomic-free scatter using precomputed ranks, 4 edges/thread
__global__ void k_scatter(const int4* __restrict__ erow4,
                          const int4* __restrict__ ecol4,
                          const float4* __restrict__ ew4) {
    int t = blockIdx.x * blockDim.x + threadIdx.x;
    if (t < N_EDGES / 4) {
        int4    r  = erow4[t];
        int4    c  = ecol4[t];
        float4  w  = ew4[t];
        ushort4 rk = ((const ushort4*)g_rank)[t];
        const float s = 1.0f - ALPHA;
        g_cw[g_rowptr[r.x] + rk.x] = make_int2(c.x, __float_as_int(s * w.x));
        g_cw[g_rowptr[r.y] + rk.y] = make_int2(c.y, __float_as_int(s * w.y));
        g_cw[g_rowptr[r.z] + rk.z] = make_int2(c.z, __float_as_int(s * w.z));
        g_cw[g_rowptr[r.w] + rk.w] = make_int2(c.w, __float_as_int(s * w.w));
    }
}

// -------- SpMM: warp per row; two 16-lane halves, 4 feats/lane --------
// SRC_F16 / DST_F16 select the storage format of the h operands.
template<bool SRC_F16, bool DST_F16>
__global__ void __launch_bounds__(256)
k_spmm(const void* __restrict__ srcp, const float* __restrict__ x,
       void* __restrict__ dstp) {
    int warp = (blockIdx.x * blockDim.x + threadIdx.x) >> 5;
    int lane = threadIdx.x & 31;
    if (warp >= N_NODES) return;

    int beg = g_rowptr[warp];
    int end = g_rowptr[warp + 1];

    int half = lane >> 4;   // which half-warp
    int sub  = lane & 15;   // 4-feature group: feats sub*4 .. sub*4+3

    float4 acc = make_float4(0.f, 0.f, 0.f, 0.f);
    const float4* __restrict__ src32 = (const float4*)srcp;
    const uint2*  __restrict__ src16 = (const uint2*)srcp;

    for (int base = beg; base < end; base += 32) {
        int e = base + lane;
        int2 cw = (e < end) ? g_cw[e] : make_int2(0, 0);
        int m = end - base; if (m > 32) m = 32;
        int steps = (m + 1) >> 1;          // halves interleave edges 2j+half
        #pragma unroll 4
        for (int j = 0; j < steps; j++) {
            int srcl = 2 * j + half;
            int   c  = __shfl_sync(0xffffffffu, cw.x, srcl);
            float wv = __int_as_float(__shfl_sync(0xffffffffu, cw.y, srcl));
            if (srcl < m) {
                float4 hv;
                if (SRC_F16) {
                    uint2 raw = src16[(size_t)c * 16 + sub];
                    float2 lo = __half22float2(*(const __half2*)&raw.x);
                    float2 hi = __half22float2(*(const __half2*)&raw.y);
                    hv = make_float4(lo.x, lo.y, hi.x, hi.y);
                } else {
                    hv = src32[(size_t)c * 16 + sub];
                }
                acc.x = fmaf(wv, hv.x, acc.x);
                acc.y = fmaf(wv, hv.y, acc.y);
                acc.z = fmaf(wv, hv.z, acc.z);
                acc.w = fmaf(wv, hv.w, acc.w);
            }
        }
    }

    // combine the two halves
    acc.x += __shfl_xor_sync(0xffffffffu, acc.x, 16);
    acc.y += __shfl_xor_sync(0xffffffffu, acc.y, 16);
    acc.z += __shfl_xor_sync(0xffffffffu, acc.z, 16);
    acc.w += __shfl_xor_sync(0xffffffffu, acc.w, 16);

    if (half == 0) {
        float4 xv = ((const float4*)x)[warp * 16 + sub];
        float4 o;
        o.x = fmaf(ALPHA, xv.x, acc.x);   // weights already carry (1-alpha)
        o.y = fmaf(ALPHA, xv.y, acc.y);
        o.z = fmaf(ALPHA, xv.z, acc.z);
        o.w = fmaf(ALPHA, xv.w, acc.w);
        if (DST_F16) {
            uint2 pk;
            *(__half2*)&pk.x = __floats2half2_rn(o.x, o.y);
            *(__half2*)&pk.y = __floats2half2_rn(o.z, o.w);
            ((uint2*)dstp)[warp * 16 + sub] = pk;
        } else {
            ((float4*)dstp)[warp * 16 + sub] = o;
        }
    }
}

extern "C" void kernel_launch(void* const* d_in, const int* in_sizes, int n_in,
                              void* d_out, int out_size) {
    const float* x    = (const float*)d_in[0];
    const int*   erow = (const int*)d_in[1];
    const int*   ecol = (const int*)d_in[2];
    const float* ew   = (const float*)d_in[3];
    float*       out  = (float*)d_out;

    float* hbuf;   cudaGetSymbolAddress((void**)&hbuf, g_h);
    __half* h16buf; cudaGetSymbolAddress((void**)&h16buf, g_h16);
    int* countPtr; cudaGetSymbolAddress((void**)&countPtr, g_count);

    float*  hA  = hbuf;
    float*  hB  = hbuf + (size_t)N_NODES * D_FEAT;
    __half* hA6 = h16buf;
    __half* hB6 = h16buf + (size_t)N_NODES * D_FEAT;

    const int TB = 256;
    const int nodeBlocks = (N_NODES + TB - 1) / TB;
    const int quadBlocks = (N_EDGES / 4 + TB - 1) / TB;
    const int spmmBlocks = (N_NODES * 32 + TB - 1) / TB;

    // CSR build (amortized over 10 SpMM iterations)
    cudaMemsetAsync(countPtr, 0, N_NODES * sizeof(int));
    k_hist<<<quadBlocks, TB>>>((const int4*)erow);
    k_scan1<<<N_SCAN_BLKS, SCAN_BLK>>>();
    k_scan2<<<1, 128>>>();
    k_scan3<<<nodeBlocks, TB>>>();
    k_scatter<<<quadBlocks, TB>>>((const int4*)erow, (const int4*)ecol,
                                  (const float4*)ew);

    // iter 1: x(f32) -> h1(f16)
    k_spmm<false, true ><<<spmmBlocks, TB>>>(x,   x, hA6);
    // iters 2-4: f16 -> f16 (h1->h2->h3->h4)
    k_spmm<true,  true ><<<spmmBlocks, TB>>>(hA6, x, hB6);
    k_spmm<true,  true ><<<spmmBlocks, TB>>>(hB6, x, hA6);
    k_spmm<true,  true ><<<spmmBlocks, TB>>>(hA6, x, hB6);
    // iter 5: f16 -> f32 (h4->h5)
    k_spmm<true,  false><<<spmmBlocks, TB>>>(hB6, x, hA);
    // iters 6-9: f32 -> f32
    k_spmm<false, false><<<spmmBlocks, TB>>>(hA,  x, hB);
    k_spmm<false, false><<<spmmBlocks, TB>>>(hB,  x, hA);
    k_spmm<false, false><<<spmmBlocks, TB>>>(hA,  x, hB);
    k_spmm<false, false><<<spmmBlocks, TB>>>(hB,  x, hA);
    // iter 10: f32 -> out
    k_spmm<false, false><<<spmmBlocks, TB>>>(hA,  x, out);
}

// round 9
// speedup vs baseline: 1.3928x; 1.3633x over previous
#include <cuda_runtime.h>
#include <cuda_fp16.h>
#include <cstdint>

// APPNP: h <- 0.9 * A@h + 0.1 * x, 10 iterations, edge-list A.
// CSR build (memset + hist-with-rank + hierarchical scan + atomic-free
// scatter), then 10x warp-per-row SpMM entirely in fp16 storage:
//   - h_k stored as fp16 scaled by 4^-k (sigma grows x2.94/iter, stored
//     values shrink x0.735/iter; scale folded into exact power-of-2 epilogue
//     constants, final iter writes unscaled fp32).
//   - gather: one 32-lane LDG.128 covers FOUR 128-byte fp16 rows
//     (quarter-warp per edge, 8 lanes x 16B per row) -> 4x fewer gather LDG
//     instructions than the fp32 path (the measured binder), and (c,w) is a
//     uniform broadcast load per quarter (L1-resident stream) -> no SHFLs in
//     the hot loop.

#define N_NODES 100000
#define N_EDGES 3200000
#define D_FEAT  64
#define ALPHA   0.1f
#define K_STEPS 10
#define SCAN_BLK 1024
#define N_SCAN_BLKS ((N_NODES + SCAN_BLK - 1) / SCAN_BLK)   // 98
#define ROW_U4 (D_FEAT / 8)   // 8 uint4 (128B) per fp16 row

// -------- static device scratch (no allocations allowed) --------
__device__ int            g_count[N_NODES];
__device__ int            g_rowptr[N_NODES + 1];
__device__ int            g_bsum[N_SCAN_BLKS];
__device__ int            g_boff[N_SCAN_BLKS];
__device__ unsigned short g_rank[N_EDGES];
__device__ int2           g_cw[N_EDGES];                    // {col, bits(0.9*w)}
__device__ uint4          g_hA[(size_t)N_NODES * ROW_U4];   // fp16 h ping
__device__ uint4          g_hB[(size_t)N_NODES * ROW_U4];   // fp16 h pong
__device__ uint4          g_x16[(size_t)N_NODES * ROW_U4];  // fp16 copy of x

// -------- CSR build --------
__global__ void k_hist(const int4* __restrict__ erow4) {
    int t = blockIdx.x * blockDim.x + threadIdx.x;
    if (t < N_EDGES / 4) {
        int4 r = erow4[t];
        unsigned short r0 = (unsigned short)atomicAdd(&g_count[r.x], 1);
        unsigned short r1 = (unsigned short)atomicAdd(&g_count[r.y], 1);
        unsigned short r2 = (unsigned short)atomicAdd(&g_count[r.z], 1);
        unsigned short r3 = (unsigned short)atomicAdd(&g_count[r.w], 1);
        ((ushort4*)g_rank)[t] = make_ushort4(r0, r1, r2, r3);
    }
}

__global__ void __launch_bounds__(SCAN_BLK) k_scan1() {
    __shared__ int s[SCAN_BLK];
    int tid = threadIdx.x;
    int i = blockIdx.x * SCAN_BLK + tid;
    int v = (i < N_NODES) ? g_count[i] : 0;
    s[tid] = v;
    __syncthreads();
    #pragma unroll
    for (int off = 1; off < SCAN_BLK; off <<= 1) {
        int t = (tid >= off) ? s[tid - off] : 0;
        __syncthreads();
        s[tid] += t;
        __syncthreads();
    }
    if (i < N_NODES) g_rowptr[i] = s[tid] - v;
    if (tid == SCAN_BLK - 1) g_bsum[blockIdx.x] = s[tid];
}

__global__ void k_scan2() {
    __shared__ int s[128];
    int tid = threadIdx.x;
    int v = (tid < N_SCAN_BLKS) ? g_bsum[tid] : 0;
    s[tid] = v;
    __syncthreads();
    #pragma unroll
    for (int off = 1; off < 128; off <<= 1) {
        int t = (tid >= off) ? s[tid - off] : 0;
        __syncthreads();
        s[tid] += t;
        __syncthreads();
    }
    if (tid < N_SCAN_BLKS) g_boff[tid] = s[tid] - v;
    if (tid == 0) g_rowptr[N_NODES] = N_EDGES;
}

__global__ void k_scan3() {
    int i = blockIdx.x * blockDim.x + threadIdx.x;
    if (i < N_NODES) g_rowptr[i] += g_boff[i >> 10];
}

__global__ void k_scatter(const int4* __restrict__ erow4,
                          const int4* __restrict__ ecol4,
                          const float4* __restrict__ ew4) {
    int t = blockIdx.x * blockDim.x + threadIdx.x;
    if (t < N_EDGES / 4) {
        int4    r  = erow4[t];
        int4    c  = ecol4[t];
        float4  w  = ew4[t];
        ushort4 rk = ((const ushort4*)g_rank)[t];
        const float s = 1.0f - ALPHA;
        g_cw[g_rowptr[r.x] + rk.x] = make_int2(c.x, __float_as_int(s * w.x));
        g_cw[g_rowptr[r.y] + rk.y] = make_int2(c.y, __float_as_int(s * w.y));
        g_cw[g_rowptr[r.z] + rk.z] = make_int2(c.z, __float_as_int(s * w.z));
        g_cw[g_rowptr[r.w] + rk.w] = make_int2(c.w, __float_as_int(s * w.w));
    }
}

// -------- x (fp32) -> fp16 --------
__global__ void k_cvt(const float4* __restrict__ xin) {
    int t = blockIdx.x * blockDim.x + threadIdx.x;
    if (t < N_NODES * D_FEAT / 8) {
        float4 a = xin[2 * t], b = xin[2 * t + 1];
        uint4 pk;
        *(__half2*)&pk.x = __floats2half2_rn(a.x, a.y);
        *(__half2*)&pk.y = __floats2half2_rn(a.z, a.w);
        *(__half2*)&pk.z = __floats2half2_rn(b.x, b.y);
        *(__half2*)&pk.w = __floats2half2_rn(b.z, b.w);
        g_x16[t] = pk;
    }
}

// -------- SpMM: warp per row; quarter-warp per edge; LDG.128 gathers -------
// src stored fp16 at scale c_in; writes dst at scale c_out.
// k1 = c_out/c_in, k2 = 0.1*c_out (both exact powers-of-2 times 0.1).
template<bool DST_F16>
__global__ void __launch_bounds__(256)
k_spmm16(const uint4* __restrict__ src, const float* __restrict__ x,
         void* __restrict__ dst, float k1, float k2) {
    int warp = (blockIdx.x * blockDim.x + threadIdx.x) >> 5;
    int lane = threadIdx.x & 31;
    if (warp >= N_NODES) return;

    int q = lane >> 3;   // quarter: which edge within each 4-edge step
    int p = lane & 7;    // feature group: feats p*8 .. p*8+7

    int beg = g_rowptr[warp];
    int end = g_rowptr[warp + 1];

    float acc0 = 0.f, acc1 = 0.f, acc2 = 0.f, acc3 = 0.f;
    float acc4 = 0.f, acc5 = 0.f, acc6 = 0.f, acc7 = 0.f;

    #pragma unroll 4
    for (int e = beg + q; e < end; e += 4) {
        int2  cw = g_cw[e];                       // uniform per quarter (L1)
        float w  = __int_as_float(cw.y);
        uint4 hv = src[(size_t)cw.x * ROW_U4 + p]; // 16B of one fp16 row
        float2 f0 = __half22float2(*(const __half2*)&hv.x);
        float2 f1 = __half22float2(*(const __half2*)&hv.y);
        float2 f2 = __half22float2(*(const __half2*)&hv.z);
        float2 f3 = __half22float2(*(const __half2*)&hv.w);
        acc0 = fmaf(w, f0.x, acc0); acc1 = fmaf(w, f0.y, acc1);
        acc2 = fmaf(w, f1.x, acc2); acc3 = fmaf(w, f1.y, acc3);
        acc4 = fmaf(w, f2.x, acc4); acc5 = fmaf(w, f2.y, acc5);
        acc6 = fmaf(w, f3.x, acc6); acc7 = fmaf(w, f3.y, acc7);
    }

    // combine the 4 quarters (disjoint edge subsets, same feature layout)
    #pragma unroll
    for (int d = 8; d <= 16; d <<= 1) {
        acc0 += __shfl_xor_sync(0xffffffffu, acc0, d);
        acc1 += __shfl_xor_sync(0xffffffffu, acc1, d);
        acc2 += __shfl_xor_sync(0xffffffffu, acc2, d);
        acc3 += __shfl_xor_sync(0xffffffffu, acc3, d);
        acc4 += __shfl_xor_sync(0xffffffffu, acc4, d);
        acc5 += __shfl_xor_sync(0xffffffffu, acc5, d);
        acc6 += __shfl_xor_sync(0xffffffffu, acc6, d);
        acc7 += __shfl_xor_sync(0xffffffffu, acc7, d);
    }

    if (lane < 8) {
        const float4* xv = (const float4*)(x + (size_t)warp * D_FEAT + p * 8);
        float4 xa = xv[0], xb = xv[1];
        float o0 = fmaf(k2, xa.x, k1 * acc0);
        float o1 = fmaf(k2, xa.y, k1 * acc1);
        float o2 = fmaf(k2, xa.z, k1 * acc2);
        float o3 = fmaf(k2, xa.w, k1 * acc3);
        float o4 = fmaf(k2, xb.x, k1 * acc4);
        float o5 = fmaf(k2, xb.y, k1 * acc5);
        float o6 = fmaf(k2, xb.z, k1 * acc6);
        float o7 = fmaf(k2, xb.w, k1 * acc7);
        if (DST_F16) {
            uint4 pk;
            *(__half2*)&pk.x = __floats2half2_rn(o0, o1);
            *(__half2*)&pk.y = __floats2half2_rn(o2, o3);
            *(__half2*)&pk.z = __floats2half2_rn(o4, o5);
            *(__half2*)&pk.w = __floats2half2_rn(o6, o7);
            ((uint4*)dst)[(size_t)warp * ROW_U4 + p] = pk;
        } else {
            float4* d = (float4*)((float*)dst + (size_t)warp * D_FEAT + p * 8);
            d[0] = make_float4(o0, o1, o2, o3);
            d[1] = make_float4(o4, o5, o6, o7);
        }
    }
}

extern "C" void kernel_launch(void* const* d_in, const int* in_sizes, int n_in,
                              void* d_out, int out_size) {
    const float* x    = (const float*)d_in[0];
    const int*   erow = (const int*)d_in[1];
    const int*   ecol = (const int*)d_in[2];
    const float* ew   = (const float*)d_in[3];
    float*       out  = (float*)d_out;

    uint4 *hA, *hB, *x16;
    int* countPtr;
    cudaGetSymbolAddress((void**)&hA, g_hA);
    cudaGetSymbolAddress((void**)&hB, g_hB);
    cudaGetSymbolAddress((void**)&x16, g_x16);
    cudaGetSymbolAddress((void**)&countPtr, g_count);

    const int TB = 256;
    const int nodeBlocks = (N_NODES + TB - 1) / TB;
    const int quadBlocks = (N_EDGES / 4 + TB - 1) / TB;
    const int cvtBlocks  = (N_NODES * D_FEAT / 8 + TB - 1) / TB;
    const int spmmBlocks = (N_NODES * 32 + TB - 1) / TB;

    // CSR build
    cudaMemsetAsync(countPtr, 0, N_NODES * sizeof(int));
    k_hist<<<quadBlocks, TB>>>((const int4*)erow);
    k_scan1<<<N_SCAN_BLKS, SCAN_BLK>>>();
    k_scan2<<<1, 128>>>();
    k_scan3<<<nodeBlocks, TB>>>();
    k_scatter<<<quadBlocks, TB>>>((const int4*)erow, (const int4*)ecol,
                                  (const float4*)ew);
    k_cvt<<<cvtBlocks, TB>>>((const float4*)x);

    // 10 propagation steps, all fp16 storage, scale c_k = 4^-k (c_10 = 1).
    // k1 = c_k/c_{k-1}, k2 = 0.1*c_k.  Weights already carry (1-alpha).
    const uint4* src = x16;
    uint4* bufs[2] = { hA, hB };
    for (int k = 1; k <= K_STEPS; k++) {
        if (k < K_STEPS) {
            float c_k = exp2f(-2.0f * k);
            uint4* dst = bufs[k & 1];
            k_spmm16<true><<<spmmBlocks, TB>>>(src, x, dst, 0.25f, 0.1f * c_k);
            src = dst;
        } else {
            float k1 = exp2f(2.0f * (K_STEPS - 1));   // 1/c_9 = 2^18
            k_spmm16<false><<<spmmBlocks, TB>>>(src, x, out, k1, 0.1f);
        }
    }
}